// round 10
// baseline (speedup 1.0000x reference)
#include <cuda_runtime.h>
#include <cuda_fp16.h>
#include <cstdint>
#include <cstddef>

// Problem constants: B=4, I=64, O=64, K=3, H=W=512.
#define EPS_F 1e-8f

// ---------------------------------------------------------------------------
// Device scratch: modulated weights packed for LDS.64 B-fetch.
// g_wB[b][t(4)][ks(36)][col=o(64)][2 words]; for K16-step ks, word0 = half2 of
// kpair row (8*ks + t), word1 = kpair row (8*ks + t + 4).
// ---------------------------------------------------------------------------
__device__ __align__(16) uint32_t g_wB[4 * 4 * 36 * 64 * 2];         // 294 KB

__device__ __forceinline__ uint32_t smem_u32(const void* p) {
    uint32_t a;
    asm("{ .reg .u64 t; cvta.to.shared.u64 t, %1; cvt.u32.u64 %0, t; }"
        : "=r"(a) : "l"(p));
    return a;
}

// ---------------------------------------------------------------------------
// Kernel 1: modulate + demodulate -> packed fp16 B tiles.
// ---------------------------------------------------------------------------
__global__ void modulate_kernel(const float* __restrict__ weight,   // (O=64, I=64, 3, 3)
                                const float* __restrict__ style) {  // (B=4, I=64)
    const int bo  = blockIdx.x;
    const int b   = bo >> 6;
    const int o   = bo & 63;
    const int tid = threadIdx.x;

    __shared__ float red[8];
    __shared__ float s_inv;

    float sum = 0.f;
    for (int idx = tid; idx < 576; idx += 256) {
        const int i = idx / 9;
        const float v = weight[o * 576 + idx] * style[b * 64 + i];
        sum += v * v;
    }
    #pragma unroll
    for (int off = 16; off; off >>= 1)
        sum += __shfl_down_sync(0xffffffffu, sum, off);
    if ((tid & 31) == 0) red[tid >> 5] = sum;
    __syncthreads();
    if (tid == 0) {
        float t = 0.f;
        #pragma unroll
        for (int k = 0; k < 8; k++) t += red[k];
        s_inv = rsqrtf(EPS_F + t);
    }
    __syncthreads();
    const float inv = s_inv;

    for (int idx = tid; idx < 288; idx += 256) {
        const int ip  = idx / 9;          // input-channel pair 0..31
        const int tap = idx - ip * 9;     // ky*3+kx
        const int i0  = 2 * ip;
        const float v0 = weight[o * 576 + i0 * 9 + tap]       * style[b * 64 + i0]     * inv;
        const float v1 = weight[o * 576 + (i0 + 1) * 9 + tap] * style[b * 64 + i0 + 1] * inv;
        __half2 h = __floats2half2_rn(v0, v1);
        const int kc = ip >> 3;           // K16 step within tap
        const int r  = ip & 7;            // kpair row within step
        const int t  = r & 3;
        const int hf = r >> 2;            // 0 -> word0, 1 -> word1
        const int ks = tap * 4 + kc;
        g_wB[(size_t)b * 18432 + (size_t)((t * 36 + ks) * 64 + o) * 2 + hf] =
            *reinterpret_cast<uint32_t*>(&h);
    }
}

// ---------------------------------------------------------------------------
// Kernel 2: fp16 mma.sync implicit-GEMM conv, direct from NCHW fp32.
//
// CTA: 256 threads, output tile 8 rows x 16 cols (M=128 px), N=64, K=576.
// Phase 1: NCHW fp32 float4 chunks (gx in [x0-4, x0+20), wholly in/out) ->
//          cvt f16x2 -> STS.64 into channel-major staging Sst[ch][r][24px],
//          ch stride 496 B (31x16B: conflict-free ldmatrix rows).
// Phase 2: ldmatrix.m8n8.x4.trans on 8ch x 8px blocks -> each lane reg holds
//          {ch,ch+1} at one pixel -> STS.32 into pixel-major A tile
//          Ash[p = r*18+f][72 halves] (144 B stride), f = px-3 when 0<=f<18.
// Then:    B tiles loaded into the region overlapping the (dead) staging.
// Mainloop/epilogue: identical to round 7 (ldmatrix A + LDS.64 B + mma,
//          A fragments double-buffered one K16-step ahead).
// ---------------------------------------------------------------------------
static constexpr int ASH_BYTES  = 180 * 144;              // 25920
static constexpr int SST_STRIDE = 496;                    // bytes per channel
static constexpr int SST_BYTES  = 64 * SST_STRIDE;        // 31744 (inside B region)
static constexpr int B_TSTRIDE  = 36 * 64 * 2 + 8;        // 4616 words per t block
static constexpr int BSH_BYTES  = 4 * B_TSTRIDE * 4;      // 73856
static constexpr int CONV_SMEM  = ASH_BYTES + BSH_BYTES;  // 99776

__global__ __launch_bounds__(256, 2)
void conv_kernel(const float* __restrict__ input,   // (4, 64, 512, 512) fp32 NCHW
                 float* __restrict__ out) {         // (4, 64, 512, 512)
    extern __shared__ __align__(16) char dsm[];
    char*      Ash = dsm;
    char*      Sst = dsm + ASH_BYTES;                      // staging (phase 1-2)
    uint32_t*  Bsh = reinterpret_cast<uint32_t*>(dsm + ASH_BYTES);  // B (after)

    const int tid  = threadIdx.x;
    const int lane = tid & 31;
    const int wid  = tid >> 5;
    const int b    = blockIdx.z;
    const int y0   = blockIdx.y << 3;
    const int x0   = blockIdx.x << 4;

    // ---- phase 1: NCHW fp32 -> channel-major fp16 staging ----
    // item = (ch, r in [0,10), c in [0,6)): float4 at gy=y0-1+r, gx0=x0-4+4c.
    {
        const float* in_b = input + (size_t)b * (64 * 512 * 512);
        #pragma unroll
        for (int it = 0; it < 15; it++) {               // 3840 items exactly
            const int idx = it * 256 + tid;
            const int ch  = idx / 60;
            const int rem = idx - ch * 60;
            const int r   = rem / 6;
            const int c   = rem - r * 6;
            const int gy  = y0 - 1 + r;
            const int gx0 = x0 - 4 + 4 * c;
            float4 v = make_float4(0.f, 0.f, 0.f, 0.f);
            if ((unsigned)gy < 512u && (unsigned)gx0 < 512u)
                v = *reinterpret_cast<const float4*>(
                        in_b + ((size_t)ch << 18) + ((size_t)gy << 9) + gx0);
            __half2 h01 = __floats2half2_rn(v.x, v.y);
            __half2 h23 = __floats2half2_rn(v.z, v.w);
            *reinterpret_cast<uint2*>(Sst + ch * SST_STRIDE + r * 48 + c * 8) =
                make_uint2(*reinterpret_cast<uint32_t*>(&h01),
                           *reinterpret_cast<uint32_t*>(&h23));
        }
    }
    __syncthreads();

    // ---- phase 2: smem transpose via ldmatrix.trans ----
    // 240 blocks (r 0..9, pxb 0..2, chb 0..7) = 60 x4 instrs; warp w does
    // i = w, w+8, ... (warp-uniform trip counts).
    {
        const uint32_t sstu = smem_u32(Sst);
        const uint32_t ashu = smem_u32(Ash);
        for (int i = wid; i < 60; i += 8) {
            const int bi  = 4 * i + (lane >> 3);        // this lane's matrix
            const int chb = bi & 7;
            const int pxb = (bi >> 3) % 3;
            const int r   = bi / 24;
            const uint32_t src = sstu
                + (uint32_t)((chb * 8 + (lane & 7)) * SST_STRIDE + r * 48 + pxb * 16);
            uint32_t q[4];
            asm volatile(
                "ldmatrix.sync.aligned.m8n8.x4.trans.shared.b16 {%0,%1,%2,%3}, [%4];"
                : "=r"(q[0]), "=r"(q[1]), "=r"(q[2]), "=r"(q[3]) : "r"(src));
            #pragma unroll
            for (int m = 0; m < 4; m++) {
                const int bm   = 4 * i + m;
                const int chb2 = bm & 7;
                const int pxb2 = (bm >> 3) % 3;
                const int r2   = bm / 24;
                const int f    = pxb2 * 8 + (lane >> 2) - 3;   // tile px
                if ((unsigned)f < 18u) {
                    const uint32_t dst = ashu
                        + (uint32_t)((r2 * 18 + f) * 144
                                     + (chb2 * 8 + 2 * (lane & 3)) * 2);
                    asm volatile("st.shared.u32 [%0], %1;" :: "r"(dst), "r"(q[m]));
                }
            }
        }
    }
    __syncthreads();

    // ---- load B: 18432 words -> padded t-blocks (overwrites staging) ----
    {
        const uint4* src = reinterpret_cast<const uint4*>(g_wB + (size_t)b * 18432);
        #pragma unroll
        for (int it = 0; it < 18; it++) {                // 4608 uint4
            const int i4  = it * 256 + tid;
            const int t   = i4 / 1152;
            const int rm  = i4 - t * 1152;
            *(reinterpret_cast<uint4*>(Bsh + t * B_TSTRIDE) + rm) = src[i4];
        }
    }
    __syncthreads();

    const int wm = wid & 3;    // m: tile rows 2wm, 2wm+1
    const int wn = wid >> 2;   // n: o range [wn*32, wn*32+32)

    float acc[2][4][4];
    #pragma unroll
    for (int mi = 0; mi < 2; mi++)
        #pragma unroll
        for (int ni = 0; ni < 4; ni++)
            #pragma unroll
            for (int j = 0; j < 4; j++) acc[mi][ni][j] = 0.f;

    // ldmatrix lane addresses: row = pixel x-offset (lane&15), col-half = lane>>4.
    const uint32_t ashu = smem_u32(Ash);
    uint32_t aBase[2];
    #pragma unroll
    for (int mi = 0; mi < 2; mi++)
        aBase[mi] = ashu + (uint32_t)(((2 * wm + mi) * 18 + (lane & 15)) * 144)
                         + (uint32_t)((lane >> 4) * 16);

    // B lane base (word index): t = lane&3 block, col = wn*32 + (lane>>2)
    const uint32_t* Blane = Bsh + (lane & 3) * B_TSTRIDE
                                + (wn * 32 + (lane >> 2)) * 2;

    #define A_ADDR(mi, ks) (aBase[mi] \
        + (uint32_t)(((((ks) >> 2) / 3) * 18 + (((ks) >> 2) % 3)) * 144) \
        + (uint32_t)(((ks) & 3) * 32))
    #define LDSM4(dst, addr) \
        asm volatile("ldmatrix.sync.aligned.m8n8.x4.shared.b16 {%0,%1,%2,%3}, [%4];" \
            : "=r"((dst)[0]), "=r"((dst)[1]), "=r"((dst)[2]), "=r"((dst)[3]) \
            : "r"(addr))

    uint32_t af[2][2][4];    // [parity][mi][frag]
    LDSM4(af[0][0], A_ADDR(0, 0));
    LDSM4(af[0][1], A_ADDR(1, 0));

    #pragma unroll
    for (int ks = 0; ks < 36; ks++) {
        const int cur = ks & 1;
        const int nxt = cur ^ 1;
        if (ks < 35) {                       // prefetch next step's A fragments
            LDSM4(af[nxt][0], A_ADDR(0, ks + 1));
            LDSM4(af[nxt][1], A_ADDR(1, ks + 1));
        }
        const uint32_t* Bks = Blane + ks * 128;
        uint2 bv[4];
        #pragma unroll
        for (int ni = 0; ni < 4; ni++)
            bv[ni] = *reinterpret_cast<const uint2*>(Bks + ni * 16);

        #pragma unroll
        for (int ni = 0; ni < 4; ni++)
            #pragma unroll
            for (int mi = 0; mi < 2; mi++)
                asm volatile(
                    "mma.sync.aligned.m16n8k16.row.col.f32.f16.f16.f32 "
                    "{%0,%1,%2,%3}, {%4,%5,%6,%7}, {%8,%9}, {%0,%1,%2,%3};"
                    : "+f"(acc[mi][ni][0]), "+f"(acc[mi][ni][1]),
                      "+f"(acc[mi][ni][2]), "+f"(acc[mi][ni][3])
                    : "r"(af[cur][mi][0]), "r"(af[cur][mi][1]),
                      "r"(af[cur][mi][2]), "r"(af[cur][mi][3]),
                      "r"(bv[ni].x), "r"(bv[ni].y));
    }
    #undef A_ADDR
    #undef LDSM4

    // ---- epilogue: c0,c1 -> (x, o), (x, o+1); c2,c3 -> (x+8, o), (x+8, o+1) ----
    const int xg = x0 + (lane >> 2);
    const int og = wn * 32 + 2 * (lane & 3);
    #pragma unroll
    for (int mi = 0; mi < 2; mi++) {
        const int y = y0 + 2 * wm + mi;
        #pragma unroll
        for (int ni = 0; ni < 4; ni++) {
            float* p = out + ((size_t)(b * 64 + og + ni * 8) << 18)
                           + ((size_t)y << 9) + xg;
            p[0]               = acc[mi][ni][0];
            p[(size_t)1 << 18] = acc[mi][ni][1];
            p[8]               = acc[mi][ni][2];
            p[((size_t)1 << 18) + 8] = acc[mi][ni][3];
        }
    }
}

// ---------------------------------------------------------------------------
// Harness entry point.
//   d_in[0] = input  (4, 64, 512, 512) float
//   d_in[1] = style  (4, 64)           float
//   d_in[2] = weight (64, 64, 3, 3)    float
//   d_out   = (4, 64, 512, 512) float
// ---------------------------------------------------------------------------
extern "C" void kernel_launch(void* const* d_in, const int* in_sizes, int n_in,
                              void* d_out, int out_size) {
    const float* input  = (const float*)d_in[0];
    const float* style  = (const float*)d_in[1];
    const float* weight = (const float*)d_in[2];
    float* out = (float*)d_out;

    cudaFuncSetAttribute(conv_kernel, cudaFuncAttributeMaxDynamicSharedMemorySize,
                         CONV_SMEM);

    modulate_kernel<<<256, 256>>>(weight, style);
    conv_kernel<<<dim3(32, 64, 4), 256, CONV_SMEM>>>(input, out);
}

// round 11
// speedup vs baseline: 1.3399x; 1.3399x over previous
#include <cuda_runtime.h>
#include <cuda_fp16.h>
#include <cstdint>
#include <cstddef>

// Problem constants: B=4, I=64, O=64, K=3, H=W=512.
#define EPS_F 1e-8f

// ---------------------------------------------------------------------------
// Device scratch: x-Winograd-transformed modulated weights, packed for the
// mma B-fragment (same (t, hf) packing as the proven direct kernel):
// g_wU[b][xi(4)][t(4)][ks(12)][o(64)][2 words], ks = ky*4 + kc, kpair = c/2:
// word0 = half2 of kpair row (8*ks + t), word1 = kpair row (8*ks + t + 4).
// ---------------------------------------------------------------------------
__device__ __align__(16) uint32_t g_wU[4 * 4 * 6144];                // 384 KB

__device__ __forceinline__ uint32_t smem_u32(const void* p) {
    uint32_t a;
    asm("{ .reg .u64 t; cvta.to.shared.u64 t, %1; cvt.u32.u64 %0, t; }"
        : "=r"(a) : "l"(p));
    return a;
}

// ---------------------------------------------------------------------------
// Kernel 1: modulate + demodulate + x-Winograd weight transform (U = G g).
// U0 = g0; U1 = (g0+g1+g2)/2; U2 = (g0-g1+g2)/2; U3 = g2   (per ky, per ch).
// ---------------------------------------------------------------------------
__global__ void modulate_kernel(const float* __restrict__ weight,   // (O=64, I=64, 3, 3)
                                const float* __restrict__ style) {  // (B=4, I=64)
    const int bo  = blockIdx.x;
    const int b   = bo >> 6;
    const int o   = bo & 63;
    const int tid = threadIdx.x;

    __shared__ float red[8];
    __shared__ float s_inv;

    float sum = 0.f;
    for (int idx = tid; idx < 576; idx += 256) {
        const int i = idx / 9;
        const float v = weight[o * 576 + idx] * style[b * 64 + i];
        sum += v * v;
    }
    #pragma unroll
    for (int off = 16; off; off >>= 1)
        sum += __shfl_down_sync(0xffffffffu, sum, off);
    if ((tid & 31) == 0) red[tid >> 5] = sum;
    __syncthreads();
    if (tid == 0) {
        float t = 0.f;
        #pragma unroll
        for (int k = 0; k < 8; k++) t += red[k];
        s_inv = rsqrtf(EPS_F + t);
    }
    __syncthreads();
    const float inv = s_inv;

    // 96 items: (cpair cp 0..31, ky 0..2)
    if (tid < 96) {
        const int cp = tid / 3;
        const int ky = tid - 3 * cp;
        const int c0 = 2 * cp;
        const float s0 = style[b * 64 + c0] * inv;
        const float s1 = style[b * 64 + c0 + 1] * inv;
        const float* w0 = weight + (o * 64 + c0) * 9 + ky * 3;
        const float g00 = w0[0] * s0, g01 = w0[1] * s0, g02 = w0[2] * s0;
        const float g10 = w0[9] * s1, g11 = w0[10] * s1, g12 = w0[11] * s1;

        float u0[4], u1[4];
        u0[0] = g00; u0[1] = 0.5f * (g00 + g01 + g02);
        u0[2] = 0.5f * (g00 - g01 + g02); u0[3] = g02;
        u1[0] = g10; u1[1] = 0.5f * (g10 + g11 + g12);
        u1[2] = 0.5f * (g10 - g11 + g12); u1[3] = g12;

        const int ks = ky * 4 + (cp >> 3);
        const int r  = cp & 7;
        const int t  = r & 3;
        const int hf = r >> 2;
        #pragma unroll
        for (int xi = 0; xi < 4; xi++) {
            __half2 h = __floats2half2_rn(u0[xi], u1[xi]);
            g_wU[(size_t)(b * 4 + xi) * 6144 + (size_t)((t * 12 + ks) * 64 + o) * 2 + hf] =
                *reinterpret_cast<uint32_t*>(&h);
        }
    }
}

// ---------------------------------------------------------------------------
// Kernel 2: x-Winograd F(2,3) fp16 mma.sync conv, direct from NCHW fp32.
//
// CTA: 256 threads, output tile 8 rows x 16 px, N=64. M = 64 x-tiles
// (8 rows x 8 tiles of 2 px). For each Winograd coord xi (4):
//   M_xi[tile][o] = sum_{ky,c} V_xi[row(tile)+ky][xt(tile)][c] * U_xi[ky][c][o]
// (GEMM K = 192 = 12 K16-steps), then Y accumulated with A^T coeffs:
//   y(2xt)   = M0+M1+M2 ;  y(2xt+1) = M1-M2-M3.
//
// V smem: V[xi][r(10)][xt(8)][c(64)] fp16, xt stride 144 B, row stride 1168 B
//   (both ldmatrix-conflict-free). Built from NCHW via aligned float4 loads:
//   V0=d0-d2, V1=d1+d2, V2=d2-d1, V3=d1-d3 over 4 consecutive x.
// U smem: 2 x 24 KB double buffer, cp.async-prefetched one xi ahead,
//   t-block stride 1544 words (conflict-free LDS.64).
// Warp (wm = wid&3, wn = wid>>2): m16 = rows {2wm,2wm+1} x 8 xt; n32.
// ---------------------------------------------------------------------------
static constexpr int V_ROW_STRIDE = 8 * 144 + 16;        // 1168 B
static constexpr int V_XI_STRIDE  = 10 * V_ROW_STRIDE;   // 11680 B
static constexpr int V_BYTES      = 4 * V_XI_STRIDE;     // 46720
static constexpr int U_TSTRIDE    = 12 * 64 * 2 + 8;     // 1544 words
static constexpr int U_BUF_WORDS  = 4 * U_TSTRIDE;       // 6176
static constexpr int CONV_SMEM    = V_BYTES + 2 * U_BUF_WORDS * 4;  // 96128

__global__ __launch_bounds__(256, 2)
void conv_kernel(const float* __restrict__ input,   // (4, 64, 512, 512) fp32 NCHW
                 float* __restrict__ out) {         // (4, 64, 512, 512)
    extern __shared__ __align__(16) char dsm[];
    uint32_t* Usm = reinterpret_cast<uint32_t*>(dsm + V_BYTES);

    const int tid  = threadIdx.x;
    const int lane = tid & 31;
    const int wid  = tid >> 5;
    const int b    = blockIdx.z;
    const int y0   = blockIdx.y << 3;
    const int x0   = blockIdx.x << 4;

    const uint32_t vsm0 = smem_u32(dsm);
    const uint32_t usm0 = smem_u32(Usm);

    // ---- kick off U0 async copy (overlaps V build) ----
    {
        const uint4* src = reinterpret_cast<const uint4*>(g_wU + (size_t)(b * 4) * 6144);
        #pragma unroll
        for (int it = 0; it < 6; it++) {
            const int i4 = it * 256 + tid;
            const int t  = i4 / 384;
            const int rm = i4 - t * 384;
            asm volatile("cp.async.cg.shared.global [%0], [%1], 16;"
                :: "r"(usm0 + (uint32_t)((t * U_TSTRIDE + rm * 4) * 4)),
                   "l"(src + i4) : "memory");
        }
        asm volatile("cp.async.commit_group;" ::: "memory");
    }

    // ---- build V from NCHW fp32 ----
    // item = (r 0..9, cpair 0..31, xhalf 0..1): 640 items.
    {
        const float* in_b = input + (size_t)b * (64 * 512 * 512);
        #pragma unroll
        for (int it = 0; it < 3; it++) {
            const int idx = it * 256 + tid;
            if (idx < 640) {
                const int r   = idx >> 6;
                const int rm  = idx & 63;
                const int cp  = rm >> 1;
                const int xh  = rm & 1;
                const int gy  = y0 - 1 + r;
                const int gxb = x0 + 8 * xh - 4;
                const bool rowok = ((unsigned)gy < 512u);
                const float* p0 = in_b + ((size_t)(2 * cp) << 18) + ((size_t)gy << 9);
                const float* p1 = p0 + ((size_t)1 << 18);
                float f0[16], f1[16];
                #pragma unroll
                for (int q = 0; q < 4; q++) {
                    const int gx = gxb + 4 * q;
                    float4 v0 = make_float4(0.f, 0.f, 0.f, 0.f);
                    float4 v1 = make_float4(0.f, 0.f, 0.f, 0.f);
                    if (rowok && (unsigned)gx < 512u) {
                        v0 = *reinterpret_cast<const float4*>(p0 + gx);
                        v1 = *reinterpret_cast<const float4*>(p1 + gx);
                    }
                    f0[4*q] = v0.x; f0[4*q+1] = v0.y; f0[4*q+2] = v0.z; f0[4*q+3] = v0.w;
                    f1[4*q] = v1.x; f1[4*q+1] = v1.y; f1[4*q+2] = v1.z; f1[4*q+3] = v1.w;
                }
                const uint32_t vbase = vsm0 + (uint32_t)(r * V_ROW_STRIDE + cp * 4);
                #pragma unroll
                for (int xq = 0; xq < 4; xq++) {
                    const int i0 = 2 * xq + 3;             // d(-1) of window
                    const int xt = 4 * xh + xq;
                    const float a0 = f0[i0], a1 = f0[i0+1], a2 = f0[i0+2], a3 = f0[i0+3];
                    const float c0 = f1[i0], c1 = f1[i0+1], c2 = f1[i0+2], c3 = f1[i0+3];
                    __half2 h0 = __floats2half2_rn(a0 - a2, c0 - c2);
                    __half2 h1 = __floats2half2_rn(a1 + a2, c1 + c2);
                    __half2 h2 = __floats2half2_rn(a2 - a1, c2 - c1);
                    __half2 h3 = __floats2half2_rn(a1 - a3, c1 - c3);
                    const uint32_t va = vbase + (uint32_t)(xt * 144);
                    asm volatile("st.shared.u32 [%0], %1;"
                                 :: "r"(va),                 "r"(*(uint32_t*)&h0));
                    asm volatile("st.shared.u32 [%0], %1;"
                                 :: "r"(va + V_XI_STRIDE),   "r"(*(uint32_t*)&h1));
                    asm volatile("st.shared.u32 [%0], %1;"
                                 :: "r"(va + 2*V_XI_STRIDE), "r"(*(uint32_t*)&h2));
                    asm volatile("st.shared.u32 [%0], %1;"
                                 :: "r"(va + 3*V_XI_STRIDE), "r"(*(uint32_t*)&h3));
                }
            }
        }
    }
    asm volatile("cp.async.wait_group 0;" ::: "memory");
    __syncthreads();

    const int wm = wid & 3;    // m: output rows 2wm, 2wm+1
    const int wn = wid >> 2;   // n: o range [wn*32, wn*32+32)

    float Y[2][2][8];          // [yr][px 0/1][ni*2+j]
    #pragma unroll
    for (int yr = 0; yr < 2; yr++)
        #pragma unroll
        for (int px = 0; px < 2; px++)
            #pragma unroll
            for (int j = 0; j < 8; j++) Y[yr][px][j] = 0.f;

    // ldmatrix A lane base: tile t' = lane&15 -> (r_ = t'>>3, xt = t'&7).
    const uint32_t aBase = vsm0
        + (uint32_t)((2 * wm + ((lane & 15) >> 3)) * V_ROW_STRIDE
                     + ((lane & 15) & 7) * 144 + (lane >> 4) * 16);

    #define LDSM4(dst, addr) \
        asm volatile("ldmatrix.sync.aligned.m8n8.x4.shared.b16 {%0,%1,%2,%3}, [%4];" \
            : "=r"((dst)[0]), "=r"((dst)[1]), "=r"((dst)[2]), "=r"((dst)[3]) \
            : "r"(addr))

    #pragma unroll
    for (int xi = 0; xi < 4; xi++) {
        // prefetch U(xi+1) into the other buffer
        if (xi < 3) {
            const uint4* src = reinterpret_cast<const uint4*>(
                g_wU + (size_t)(b * 4 + xi + 1) * 6144);
            const uint32_t ub = usm0 + (uint32_t)(((xi + 1) & 1) * U_BUF_WORDS * 4);
            #pragma unroll
            for (int it = 0; it < 6; it++) {
                const int i4 = it * 256 + tid;
                const int t  = i4 / 384;
                const int rm = i4 - t * 384;
                asm volatile("cp.async.cg.shared.global [%0], [%1], 16;"
                    :: "r"(ub + (uint32_t)((t * U_TSTRIDE + rm * 4) * 4)),
                       "l"(src + i4) : "memory");
            }
            asm volatile("cp.async.commit_group;" ::: "memory");
        }

        float m[4][4];
        #pragma unroll
        for (int ni = 0; ni < 4; ni++)
            #pragma unroll
            for (int j = 0; j < 4; j++) m[ni][j] = 0.f;

        const uint32_t vX = aBase + (uint32_t)(xi * V_XI_STRIDE);
        const uint32_t* Blane = Usm + (xi & 1) * U_BUF_WORDS
                              + (lane & 3) * U_TSTRIDE + (wn * 32 + (lane >> 2)) * 2;

        uint32_t af[2][4];
        LDSM4(af[0], vX);                                  // ks=0
        #pragma unroll
        for (int ks = 0; ks < 12; ks++) {
            const int cur = ks & 1, nxt = cur ^ 1;
            if (ks < 11) {
                const int k1 = ks + 1;
                LDSM4(af[nxt], vX + (uint32_t)((k1 >> 2) * V_ROW_STRIDE + (k1 & 3) * 32));
            }
            const uint32_t* Bks = Blane + ks * 128;
            uint2 bv[4];
            #pragma unroll
            for (int ni = 0; ni < 4; ni++)
                bv[ni] = *reinterpret_cast<const uint2*>(Bks + ni * 16);
            #pragma unroll
            for (int ni = 0; ni < 4; ni++)
                asm volatile(
                    "mma.sync.aligned.m16n8k16.row.col.f32.f16.f16.f32 "
                    "{%0,%1,%2,%3}, {%4,%5,%6,%7}, {%8,%9}, {%0,%1,%2,%3};"
                    : "+f"(m[ni][0]), "+f"(m[ni][1]), "+f"(m[ni][2]), "+f"(m[ni][3])
                    : "r"(af[cur][0]), "r"(af[cur][1]), "r"(af[cur][2]), "r"(af[cur][3]),
                      "r"(bv[ni].x), "r"(bv[ni].y));
        }

        // fold M_xi into Y:  px0 += {1,1,1,0}[xi]*M ;  px1 += {0,1,-1,-1}[xi]*M
        #pragma unroll
        for (int ni = 0; ni < 4; ni++) {
            if (xi <= 2) {
                Y[0][0][ni*2+0] += m[ni][0];  Y[0][0][ni*2+1] += m[ni][1];
                Y[1][0][ni*2+0] += m[ni][2];  Y[1][0][ni*2+1] += m[ni][3];
            }
            if (xi == 1) {
                Y[0][1][ni*2+0] += m[ni][0];  Y[0][1][ni*2+1] += m[ni][1];
                Y[1][1][ni*2+0] += m[ni][2];  Y[1][1][ni*2+1] += m[ni][3];
            } else if (xi >= 2) {
                Y[0][1][ni*2+0] -= m[ni][0];  Y[0][1][ni*2+1] -= m[ni][1];
                Y[1][1][ni*2+0] -= m[ni][2];  Y[1][1][ni*2+1] -= m[ni][3];
            }
        }

        if (xi < 3) {
            asm volatile("cp.async.wait_group 0;" ::: "memory");
            __syncthreads();
        }
    }
    #undef LDSM4

    // ---- epilogue: STG.64 of adjacent output-px pairs (fully coalesced) ----
    const int xg = x0 + 2 * (lane >> 2);
    #pragma unroll
    for (int yr = 0; yr < 2; yr++) {
        const int y = y0 + 2 * wm + yr;
        #pragma unroll
        for (int ni = 0; ni < 4; ni++)
            #pragma unroll
            for (int j = 0; j < 2; j++) {
                const int o = wn * 32 + ni * 8 + 2 * (lane & 3) + j;
                float2 v = make_float2(Y[yr][0][ni*2+j], Y[yr][1][ni*2+j]);
                *reinterpret_cast<float2*>(
                    out + ((size_t)(b * 64 + o) << 18) + ((size_t)y << 9) + xg) = v;
            }
    }
}

// ---------------------------------------------------------------------------
// Harness entry point.
//   d_in[0] = input  (4, 64, 512, 512) float
//   d_in[1] = style  (4, 64)           float
//   d_in[2] = weight (64, 64, 3, 3)    float
//   d_out   = (4, 64, 512, 512) float
// ---------------------------------------------------------------------------
extern "C" void kernel_launch(void* const* d_in, const int* in_sizes, int n_in,
                              void* d_out, int out_size) {
    const float* input  = (const float*)d_in[0];
    const float* style  = (const float*)d_in[1];
    const float* weight = (const float*)d_in[2];
    float* out = (float*)d_out;

    cudaFuncSetAttribute(conv_kernel, cudaFuncAttributeMaxDynamicSharedMemorySize,
                         CONV_SMEM);

    modulate_kernel<<<256, 256>>>(weight, style);
    conv_kernel<<<dim3(32, 64, 4), 256, CONV_SMEM>>>(input, out);
}

// round 12
// speedup vs baseline: 1.4233x; 1.0623x over previous
#include <cuda_runtime.h>
#include <cuda_fp16.h>
#include <cstdint>
#include <cstddef>

// Problem constants: B=4, I=64, O=64, K=3, H=W=512.
#define EPS_F 1e-8f

// ---------------------------------------------------------------------------
// Device scratch: x-Winograd-transformed modulated weights, laid out so one
// mma B fragment = one coalesced LDG.64:
// g_wU[b][xi(4)][ks(12)][ni(8)][lane(32)][w(2)] (uint32 words), where for
// fragment (ks, ni), lane l supplies kpair rows (l&3)+4w of the K16 step and
// output channel o = ni*8 + (l>>2).  xi=3 is stored NEGATED (A^T fold).
// ---------------------------------------------------------------------------
__device__ __align__(16) uint32_t g_wU[4 * 4 * 6144];                // 384 KB

__device__ __forceinline__ uint32_t smem_u32(const void* p) {
    uint32_t a;
    asm("{ .reg .u64 t; cvta.to.shared.u64 t, %1; cvt.u32.u64 %0, t; }"
        : "=r"(a) : "l"(p));
    return a;
}

// ---------------------------------------------------------------------------
// Kernel 1: modulate + demodulate + x-Winograd weight transform (U = G g).
// U0 = g0; U1 = (g0+g1+g2)/2; U2 = (g0-g1+g2)/2; U3 = g2 (U3 stored negated).
// ---------------------------------------------------------------------------
__global__ void modulate_kernel(const float* __restrict__ weight,   // (O=64, I=64, 3, 3)
                                const float* __restrict__ style) {  // (B=4, I=64)
    const int bo  = blockIdx.x;
    const int b   = bo >> 6;
    const int o   = bo & 63;
    const int tid = threadIdx.x;

    __shared__ float red[8];
    __shared__ float s_inv;

    float sum = 0.f;
    for (int idx = tid; idx < 576; idx += 256) {
        const int i = idx / 9;
        const float v = weight[o * 576 + idx] * style[b * 64 + i];
        sum += v * v;
    }
    #pragma unroll
    for (int off = 16; off; off >>= 1)
        sum += __shfl_down_sync(0xffffffffu, sum, off);
    if ((tid & 31) == 0) red[tid >> 5] = sum;
    __syncthreads();
    if (tid == 0) {
        float t = 0.f;
        #pragma unroll
        for (int k = 0; k < 8; k++) t += red[k];
        s_inv = rsqrtf(EPS_F + t);
    }
    __syncthreads();
    const float inv = s_inv;

    // 96 items: (cpair cp 0..31, ky 0..2)
    if (tid < 96) {
        const int cp = tid / 3;
        const int ky = tid - 3 * cp;
        const int c0 = 2 * cp;
        const float s0 = style[b * 64 + c0] * inv;
        const float s1 = style[b * 64 + c0 + 1] * inv;
        const float* w0 = weight + (o * 64 + c0) * 9 + ky * 3;
        const float g00 = w0[0] * s0, g01 = w0[1] * s0, g02 = w0[2] * s0;
        const float g10 = w0[9] * s1, g11 = w0[10] * s1, g12 = w0[11] * s1;

        float u0[4], u1[4];
        u0[0] = g00; u0[1] = 0.5f * (g00 + g01 + g02);
        u0[2] = 0.5f * (g00 - g01 + g02); u0[3] = -g02;    // xi=3 negated
        u1[0] = g10; u1[1] = 0.5f * (g10 + g11 + g12);
        u1[2] = 0.5f * (g10 - g11 + g12); u1[3] = -g12;    // xi=3 negated

        const int ks = ky * 4 + (cp >> 3);
        const int r  = cp & 7;
        const int w  = r >> 2;                  // word slot
        const int t  = r & 3;
        const int ni = o >> 3;
        const int ln = ((o & 7) << 2) | t;      // lane that consumes this word
        #pragma unroll
        for (int xi = 0; xi < 4; xi++) {
            __half2 h = __floats2half2_rn(u0[xi], u1[xi]);
            g_wU[(size_t)(b * 4 + xi) * 6144
                 + (size_t)(((ks * 8 + ni) * 32 + ln) * 2 + w)] =
                *reinterpret_cast<uint32_t*>(&h);
        }
    }
}

// ---------------------------------------------------------------------------
// Kernel 2: x-Winograd F(2,3) fp16 mma.sync conv, direct from NCHW fp32.
// Barrier-free mainloop: V (transformed input) in smem; U (B operand) read
// straight from global (L2/L1-hot) via coalesced LDG.64, prefetch depth 1.
//
// CTA: 256 threads, output tile 8 rows x 16 px, N=64. M = 64 x-tiles.
// Per Winograd coord xi: GEMM M64 x N64 x K192 (12 K16-steps).
// A^T fold: xi=0 -> Y_px0 (in-place acc), xi=3 (pre-negated) -> Y_px1,
//           xi=1 -> temp, +px0 +px1;  xi=2 -> temp, +px0 -px1.
// V smem: V[xi][r(10)][xt(8)][c(64)] fp16, xt stride 144 B, row stride 1168 B.
// Warp (wm = wid&3, wn = wid>>2): m16 = rows {2wm,2wm+1} x 8 xt; n32.
// ---------------------------------------------------------------------------
static constexpr int V_ROW_STRIDE = 8 * 144 + 16;        // 1168 B
static constexpr int V_XI_STRIDE  = 10 * V_ROW_STRIDE;   // 11680 B
static constexpr int CONV_SMEM    = 4 * V_XI_STRIDE;     // 46720

#define LDSM4(dst, addr) \
    asm volatile("ldmatrix.sync.aligned.m8n8.x4.shared.b16 {%0,%1,%2,%3}, [%4];" \
        : "=r"((dst)[0]), "=r"((dst)[1]), "=r"((dst)[2]), "=r"((dst)[3]) \
        : "r"(addr))

// One xi-GEMM: 12 K16-steps, A from smem (ldmatrix, db), B from global (LDG.64,
// db), accumulating into acc[ni][4].
__device__ __forceinline__ void gemm_xi(float (&acc)[4][4], uint32_t vX,
                                        const uint2* __restrict__ Ufrag,
                                        int lane) {
    uint32_t af[2][4];
    uint2    bv[2][4];
    LDSM4(af[0], vX);
    #pragma unroll
    for (int ni = 0; ni < 4; ni++)
        bv[0][ni] = __ldg(Ufrag + ni * 32 + lane);

    #pragma unroll
    for (int ks = 0; ks < 12; ks++) {
        const int cur = ks & 1, nxt = cur ^ 1;
        if (ks < 11) {
            const int k1 = ks + 1;
            LDSM4(af[nxt], vX + (uint32_t)((k1 >> 2) * V_ROW_STRIDE + (k1 & 3) * 32));
            #pragma unroll
            for (int ni = 0; ni < 4; ni++)
                bv[nxt][ni] = __ldg(Ufrag + (k1 * 8 + ni) * 32 + lane);
        }
        #pragma unroll
        for (int ni = 0; ni < 4; ni++)
            asm volatile(
                "mma.sync.aligned.m16n8k16.row.col.f32.f16.f16.f32 "
                "{%0,%1,%2,%3}, {%4,%5,%6,%7}, {%8,%9}, {%0,%1,%2,%3};"
                : "+f"(acc[ni][0]), "+f"(acc[ni][1]),
                  "+f"(acc[ni][2]), "+f"(acc[ni][3])
                : "r"(af[cur][0]), "r"(af[cur][1]), "r"(af[cur][2]), "r"(af[cur][3]),
                  "r"(bv[cur][ni].x), "r"(bv[cur][ni].y));
    }
}

__global__ __launch_bounds__(256, 2)
void conv_kernel(const float* __restrict__ input,   // (4, 64, 512, 512) fp32 NCHW
                 float* __restrict__ out) {         // (4, 64, 512, 512)
    extern __shared__ __align__(16) char dsm[];

    const int tid  = threadIdx.x;
    const int lane = tid & 31;
    const int wid  = tid >> 5;
    const int b    = blockIdx.z;
    const int y0   = blockIdx.y << 3;
    const int x0   = blockIdx.x << 4;

    const uint32_t vsm0 = smem_u32(dsm);

    // ---- build V from NCHW fp32 ----
    // item = (r 0..9, cpair 0..31, xhalf 0..1): 640 items.
    {
        const float* in_b = input + (size_t)b * (64 * 512 * 512);
        #pragma unroll
        for (int it = 0; it < 3; it++) {
            const int idx = it * 256 + tid;
            if (idx < 640) {
                const int r   = idx >> 6;
                const int rm  = idx & 63;
                const int cp  = rm >> 1;
                const int xh  = rm & 1;
                const int gy  = y0 - 1 + r;
                const int gxb = x0 + 8 * xh - 4;
                const bool rowok = ((unsigned)gy < 512u);
                const float* p0 = in_b + ((size_t)(2 * cp) << 18) + ((size_t)gy << 9);
                const float* p1 = p0 + ((size_t)1 << 18);
                float f0[16], f1[16];
                #pragma unroll
                for (int q = 0; q < 4; q++) {
                    const int gx = gxb + 4 * q;
                    float4 v0 = make_float4(0.f, 0.f, 0.f, 0.f);
                    float4 v1 = make_float4(0.f, 0.f, 0.f, 0.f);
                    if (rowok && (unsigned)gx < 512u) {
                        v0 = *reinterpret_cast<const float4*>(p0 + gx);
                        v1 = *reinterpret_cast<const float4*>(p1 + gx);
                    }
                    f0[4*q] = v0.x; f0[4*q+1] = v0.y; f0[4*q+2] = v0.z; f0[4*q+3] = v0.w;
                    f1[4*q] = v1.x; f1[4*q+1] = v1.y; f1[4*q+2] = v1.z; f1[4*q+3] = v1.w;
                }
                const uint32_t vbase = vsm0 + (uint32_t)(r * V_ROW_STRIDE + cp * 4);
                #pragma unroll
                for (int xq = 0; xq < 4; xq++) {
                    const int i0 = 2 * xq + 3;             // d(-1) of window
                    const int xt = 4 * xh + xq;
                    const float a0 = f0[i0], a1 = f0[i0+1], a2 = f0[i0+2], a3 = f0[i0+3];
                    const float c0 = f1[i0], c1 = f1[i0+1], c2 = f1[i0+2], c3 = f1[i0+3];
                    __half2 h0 = __floats2half2_rn(a0 - a2, c0 - c2);
                    __half2 h1 = __floats2half2_rn(a1 + a2, c1 + c2);
                    __half2 h2 = __floats2half2_rn(a2 - a1, c2 - c1);
                    __half2 h3 = __floats2half2_rn(a1 - a3, c1 - c3);
                    const uint32_t va = vbase + (uint32_t)(xt * 144);
                    asm volatile("st.shared.u32 [%0], %1;"
                                 :: "r"(va),                 "r"(*(uint32_t*)&h0));
                    asm volatile("st.shared.u32 [%0], %1;"
                                 :: "r"(va + V_XI_STRIDE),   "r"(*(uint32_t*)&h1));
                    asm volatile("st.shared.u32 [%0], %1;"
                                 :: "r"(va + 2*V_XI_STRIDE), "r"(*(uint32_t*)&h2));
                    asm volatile("st.shared.u32 [%0], %1;"
                                 :: "r"(va + 3*V_XI_STRIDE), "r"(*(uint32_t*)&h3));
                }
            }
        }
    }
    __syncthreads();      // the ONLY barrier

    const int wm = wid & 3;    // m: output rows 2wm, 2wm+1
    const int wn = wid >> 2;   // n: o range [wn*32, wn*32+32)

    // ldmatrix A lane base: tile t' = lane&15 -> (r_ = t'>>3, xt = t'&7).
    const uint32_t aBase = vsm0
        + (uint32_t)((2 * wm + ((lane & 15) >> 3)) * V_ROW_STRIDE
                     + ((lane & 15) & 7) * 144 + (lane >> 4) * 16);

    // U fragment base for this warp (uint2 units; 3072 per xi)
    const uint2* Ub = reinterpret_cast<const uint2*>(g_wU)
                      + (size_t)(b * 4) * 3072 + (size_t)(wn * 4) * 32;

    float Y0[4][4], Y1[4][4];        // px0 / px1 accumulators
    #pragma unroll
    for (int ni = 0; ni < 4; ni++)
        #pragma unroll
        for (int j = 0; j < 4; j++) { Y0[ni][j] = 0.f; Y1[ni][j] = 0.f; }

    // xi = 0: directly into Y0 (px0 += M0)
    gemm_xi(Y0, aBase,                               Ub,            lane);
    // xi = 3 (pre-negated): directly into Y1 (px1 -= M3)
    gemm_xi(Y1, aBase + 3u * V_XI_STRIDE,            Ub + 3 * 3072, lane);

    // xi = 1: temp, px0 += M1, px1 += M1
    {
        float m[4][4];
        #pragma unroll
        for (int ni = 0; ni < 4; ni++)
            #pragma unroll
            for (int j = 0; j < 4; j++) m[ni][j] = 0.f;
        gemm_xi(m, aBase + 1u * V_XI_STRIDE,         Ub + 1 * 3072, lane);
        #pragma unroll
        for (int ni = 0; ni < 4; ni++)
            #pragma unroll
            for (int j = 0; j < 4; j++) { Y0[ni][j] += m[ni][j]; Y1[ni][j] += m[ni][j]; }
    }
    // xi = 2: temp, px0 += M2, px1 -= M2
    {
        float m[4][4];
        #pragma unroll
        for (int ni = 0; ni < 4; ni++)
            #pragma unroll
            for (int j = 0; j < 4; j++) m[ni][j] = 0.f;
        gemm_xi(m, aBase + 2u * V_XI_STRIDE,         Ub + 2 * 3072, lane);
        #pragma unroll
        for (int ni = 0; ni < 4; ni++)
            #pragma unroll
            for (int j = 0; j < 4; j++) { Y0[ni][j] += m[ni][j]; Y1[ni][j] -= m[ni][j]; }
    }

    // ---- epilogue: STG.64 of adjacent output-px pairs (fully coalesced) ----
    const int xg = x0 + 2 * (lane >> 2);
    #pragma unroll
    for (int yr = 0; yr < 2; yr++) {
        const int y = y0 + 2 * wm + yr;
        #pragma unroll
        for (int ni = 0; ni < 4; ni++)
            #pragma unroll
            for (int j = 0; j < 2; j++) {
                const int o = wn * 32 + ni * 8 + 2 * (lane & 3) + j;
                float2 v = make_float2(Y0[ni][yr * 2 + j], Y1[ni][yr * 2 + j]);
                *reinterpret_cast<float2*>(
                    out + ((size_t)(b * 64 + o) << 18) + ((size_t)y << 9) + xg) = v;
            }
    }
}

// ---------------------------------------------------------------------------
// Harness entry point.
//   d_in[0] = input  (4, 64, 512, 512) float
//   d_in[1] = style  (4, 64)           float
//   d_in[2] = weight (64, 64, 3, 3)    float
//   d_out   = (4, 64, 512, 512) float
// ---------------------------------------------------------------------------
extern "C" void kernel_launch(void* const* d_in, const int* in_sizes, int n_in,
                              void* d_out, int out_size) {
    const float* input  = (const float*)d_in[0];
    const float* style  = (const float*)d_in[1];
    const float* weight = (const float*)d_in[2];
    float* out = (float*)d_out;

    cudaFuncSetAttribute(conv_kernel, cudaFuncAttributeMaxDynamicSharedMemorySize,
                         CONV_SMEM);

    modulate_kernel<<<256, 256>>>(weight, style);
    conv_kernel<<<dim3(32, 64, 4), 256, CONV_SMEM>>>(input, out);
}

// round 13
// speedup vs baseline: 1.6503x; 1.1595x over previous
#include <cuda_runtime.h>
#include <cuda_fp16.h>
#include <cstdint>
#include <cstddef>

// Problem constants: B=4, I=64, O=64, K=3, H=W=512.
#define EPS_F 1e-8f

// ---------------------------------------------------------------------------
// Device scratch: x-Winograd-transformed modulated weights, laid out so one
// mma B fragment = one coalesced LDG.64:
// g_wU[b][xi(4)][ks(12)][ni(8)][lane(32)][w(2)] (uint32 words); lane l
// supplies kpair rows (l&3)+4w of K16-step ks, output channel o = ni*8+(l>>2).
// xi=3 is stored NEGATED (A^T fold).
// ---------------------------------------------------------------------------
__device__ __align__(16) uint32_t g_wU[4 * 4 * 6144];                // 384 KB

__device__ __forceinline__ uint32_t smem_u32(const void* p) {
    uint32_t a;
    asm("{ .reg .u64 t; cvta.to.shared.u64 t, %1; cvt.u32.u64 %0, t; }"
        : "=r"(a) : "l"(p));
    return a;
}

// ---------------------------------------------------------------------------
// Kernel 1: modulate + demodulate + x-Winograd weight transform (U = G g).
// U0 = g0; U1 = (g0+g1+g2)/2; U2 = (g0-g1+g2)/2; U3 = -g2 (negated).
// ---------------------------------------------------------------------------
__global__ void modulate_kernel(const float* __restrict__ weight,   // (O=64, I=64, 3, 3)
                                const float* __restrict__ style) {  // (B=4, I=64)
    const int bo  = blockIdx.x;
    const int b   = bo >> 6;
    const int o   = bo & 63;
    const int tid = threadIdx.x;

    __shared__ float red[8];
    __shared__ float s_inv;

    float sum = 0.f;
    for (int idx = tid; idx < 576; idx += 256) {
        const int i = idx / 9;
        const float v = weight[o * 576 + idx] * style[b * 64 + i];
        sum += v * v;
    }
    #pragma unroll
    for (int off = 16; off; off >>= 1)
        sum += __shfl_down_sync(0xffffffffu, sum, off);
    if ((tid & 31) == 0) red[tid >> 5] = sum;
    __syncthreads();
    if (tid == 0) {
        float t = 0.f;
        #pragma unroll
        for (int k = 0; k < 8; k++) t += red[k];
        s_inv = rsqrtf(EPS_F + t);
    }
    __syncthreads();
    const float inv = s_inv;

    // 96 items: (cpair cp 0..31, ky 0..2)
    if (tid < 96) {
        const int cp = tid / 3;
        const int ky = tid - 3 * cp;
        const int c0 = 2 * cp;
        const float s0 = style[b * 64 + c0] * inv;
        const float s1 = style[b * 64 + c0 + 1] * inv;
        const float* w0 = weight + (o * 64 + c0) * 9 + ky * 3;
        const float g00 = w0[0] * s0, g01 = w0[1] * s0, g02 = w0[2] * s0;
        const float g10 = w0[9] * s1, g11 = w0[10] * s1, g12 = w0[11] * s1;

        float u0[4], u1[4];
        u0[0] = g00; u0[1] = 0.5f * (g00 + g01 + g02);
        u0[2] = 0.5f * (g00 - g01 + g02); u0[3] = -g02;    // xi=3 negated
        u1[0] = g10; u1[1] = 0.5f * (g10 + g11 + g12);
        u1[2] = 0.5f * (g10 - g11 + g12); u1[3] = -g12;    // xi=3 negated

        const int ks = ky * 4 + (cp >> 3);
        const int r  = cp & 7;
        const int w  = r >> 2;                  // word slot
        const int t  = r & 3;
        const int ni = o >> 3;
        const int ln = ((o & 7) << 2) | t;      // lane that consumes this word
        #pragma unroll
        for (int xi = 0; xi < 4; xi++) {
            __half2 h = __floats2half2_rn(u0[xi], u1[xi]);
            g_wU[(size_t)(b * 4 + xi) * 6144
                 + (size_t)(((ks * 8 + ni) * 32 + ln) * 2 + w)] =
                *reinterpret_cast<uint32_t*>(&h);
        }
    }
}

// ---------------------------------------------------------------------------
// Kernel 2: x-Winograd F(2,3) fp16 mma.sync conv, direct from NCHW fp32.
// 128 threads = 4 warps, each m32 x n32 (2 m16-tiles): halves B-fragment L1
// traffic per mma vs the 8-warp m16 layout.
//
// CTA tile: 8 rows x 16 px, M = 64 x-tiles (8 rows x 8 tiles of 2 px).
// Per Winograd coord xi: GEMM M64 x N64 x K192 (12 K16-steps).
// A^T fold: xi=0 -> Y0 (px0), xi=3 (pre-negated) -> Y1 (px1),
//           xi=1 -> temp, +Y0 +Y1;  xi=2 -> temp, +Y0 -Y1.
// V smem: V[xi][r(10)][xt(8)][c(64)] fp16, xt stride 144 B, row stride 1168 B.
// Warp (wm = wid&1, wn = wid>>1): rows [4wm, 4wm+4) x o range [wn*32, +32).
// ---------------------------------------------------------------------------
static constexpr int V_ROW_STRIDE = 8 * 144 + 16;        // 1168 B
static constexpr int V_XI_STRIDE  = 10 * V_ROW_STRIDE;   // 11680 B
static constexpr int CONV_SMEM    = 4 * V_XI_STRIDE;     // 46720

#define LDSM4(dst, addr) \
    asm volatile("ldmatrix.sync.aligned.m8n8.x4.shared.b16 {%0,%1,%2,%3}, [%4];" \
        : "=r"((dst)[0]), "=r"((dst)[1]), "=r"((dst)[2]), "=r"((dst)[3]) \
        : "r"(addr))

// One xi-GEMM, m32n32: 12 K16-steps, A (2 m-tiles) from smem via ldmatrix,
// B from global via coalesced LDG.64; both double-buffered one step ahead.
__device__ __forceinline__ void gemm_xi(float (&acc)[2][4][4],
                                        uint32_t a0, uint32_t a1,
                                        const uint2* __restrict__ Ufrag,
                                        int lane) {
    uint32_t af[2][2][4];
    uint2    bv[2][4];
    LDSM4(af[0][0], a0);
    LDSM4(af[0][1], a1);
    #pragma unroll
    for (int ni = 0; ni < 4; ni++)
        bv[0][ni] = __ldg(Ufrag + ni * 32 + lane);

    #pragma unroll
    for (int ks = 0; ks < 12; ks++) {
        const int cur = ks & 1, nxt = cur ^ 1;
        if (ks < 11) {
            const int k1 = ks + 1;
            const uint32_t off = (uint32_t)((k1 >> 2) * V_ROW_STRIDE + (k1 & 3) * 32);
            LDSM4(af[nxt][0], a0 + off);
            LDSM4(af[nxt][1], a1 + off);
            #pragma unroll
            for (int ni = 0; ni < 4; ni++)
                bv[nxt][ni] = __ldg(Ufrag + (k1 * 8 + ni) * 32 + lane);
        }
        #pragma unroll
        for (int ni = 0; ni < 4; ni++)
            #pragma unroll
            for (int mi = 0; mi < 2; mi++)
                asm volatile(
                    "mma.sync.aligned.m16n8k16.row.col.f32.f16.f16.f32 "
                    "{%0,%1,%2,%3}, {%4,%5,%6,%7}, {%8,%9}, {%0,%1,%2,%3};"
                    : "+f"(acc[mi][ni][0]), "+f"(acc[mi][ni][1]),
                      "+f"(acc[mi][ni][2]), "+f"(acc[mi][ni][3])
                    : "r"(af[cur][mi][0]), "r"(af[cur][mi][1]),
                      "r"(af[cur][mi][2]), "r"(af[cur][mi][3]),
                      "r"(bv[cur][ni].x), "r"(bv[cur][ni].y));
    }
}

__global__ __launch_bounds__(128, 3)
void conv_kernel(const float* __restrict__ input,   // (4, 64, 512, 512) fp32 NCHW
                 float* __restrict__ out) {         // (4, 64, 512, 512)
    extern __shared__ __align__(16) char dsm[];

    const int tid  = threadIdx.x;
    const int lane = tid & 31;
    const int wid  = tid >> 5;
    const int b    = blockIdx.z;
    const int y0   = blockIdx.y << 3;
    const int x0   = blockIdx.x << 4;

    const uint32_t vsm0 = smem_u32(dsm);

    // ---- build V from NCHW fp32 ----
    // item = (r 0..9, cpair 0..31, xhalf 0..1): 640 items = 128 thr x 5.
    {
        const float* in_b = input + (size_t)b * (64 * 512 * 512);
        #pragma unroll
        for (int it = 0; it < 5; it++) {
            const int idx = it * 128 + tid;
            const int r   = idx >> 6;
            const int rm  = idx & 63;
            const int cp  = rm >> 1;
            const int xh  = rm & 1;
            const int gy  = y0 - 1 + r;
            const int gxb = x0 + 8 * xh - 4;
            const bool rowok = ((unsigned)gy < 512u);
            const float* p0 = in_b + ((size_t)(2 * cp) << 18) + ((size_t)gy << 9);
            const float* p1 = p0 + ((size_t)1 << 18);
            float f0[16], f1[16];
            #pragma unroll
            for (int q = 0; q < 4; q++) {
                const int gx = gxb + 4 * q;
                float4 v0 = make_float4(0.f, 0.f, 0.f, 0.f);
                float4 v1 = make_float4(0.f, 0.f, 0.f, 0.f);
                if (rowok && (unsigned)gx < 512u) {
                    v0 = *reinterpret_cast<const float4*>(p0 + gx);
                    v1 = *reinterpret_cast<const float4*>(p1 + gx);
                }
                f0[4*q] = v0.x; f0[4*q+1] = v0.y; f0[4*q+2] = v0.z; f0[4*q+3] = v0.w;
                f1[4*q] = v1.x; f1[4*q+1] = v1.y; f1[4*q+2] = v1.z; f1[4*q+3] = v1.w;
            }
            const uint32_t vbase = vsm0 + (uint32_t)(r * V_ROW_STRIDE + cp * 4);
            #pragma unroll
            for (int xq = 0; xq < 4; xq++) {
                const int i0 = 2 * xq + 3;             // d(-1) of window
                const int xt = 4 * xh + xq;
                const float a0 = f0[i0], a1 = f0[i0+1], a2 = f0[i0+2], a3 = f0[i0+3];
                const float c0 = f1[i0], c1 = f1[i0+1], c2 = f1[i0+2], c3 = f1[i0+3];
                __half2 h0 = __floats2half2_rn(a0 - a2, c0 - c2);
                __half2 h1 = __floats2half2_rn(a1 + a2, c1 + c2);
                __half2 h2 = __floats2half2_rn(a2 - a1, c2 - c1);
                __half2 h3 = __floats2half2_rn(a1 - a3, c1 - c3);
                const uint32_t va = vbase + (uint32_t)(xt * 144);
                asm volatile("st.shared.u32 [%0], %1;"
                             :: "r"(va),                 "r"(*(uint32_t*)&h0));
                asm volatile("st.shared.u32 [%0], %1;"
                             :: "r"(va + V_XI_STRIDE),   "r"(*(uint32_t*)&h1));
                asm volatile("st.shared.u32 [%0], %1;"
                             :: "r"(va + 2*V_XI_STRIDE), "r"(*(uint32_t*)&h2));
                asm volatile("st.shared.u32 [%0], %1;"
                             :: "r"(va + 3*V_XI_STRIDE), "r"(*(uint32_t*)&h3));
            }
        }
    }
    __syncthreads();      // the ONLY barrier

    const int wm = wid & 1;    // m: rows [4wm, 4wm+4)
    const int wn = wid >> 1;   // n: o range [wn*32, wn*32+32)

    // ldmatrix A lane bases for the 2 m16-tiles of this warp.
    const uint32_t aCom = vsm0
        + (uint32_t)((((lane & 15) & 7) * 144) + (lane >> 4) * 16);
    const uint32_t a0 = aCom
        + (uint32_t)((4 * wm + ((lane & 15) >> 3)) * V_ROW_STRIDE);
    const uint32_t a1 = a0 + (uint32_t)(2 * V_ROW_STRIDE);

    // U fragment base for this warp (uint2 units; 3072 per xi)
    const uint2* Ub = reinterpret_cast<const uint2*>(g_wU)
                      + (size_t)(b * 4) * 3072 + (size_t)(wn * 4) * 32;

    float Y0[2][4][4], Y1[2][4][4];
    #pragma unroll
    for (int mi = 0; mi < 2; mi++)
        #pragma unroll
        for (int ni = 0; ni < 4; ni++)
            #pragma unroll
            for (int j = 0; j < 4; j++) { Y0[mi][ni][j] = 0.f; Y1[mi][ni][j] = 0.f; }

    // xi = 0: directly into Y0 (px0 += M0)
    gemm_xi(Y0, a0, a1, Ub, lane);
    // xi = 3 (pre-negated): directly into Y1 (px1 -= M3)
    gemm_xi(Y1, a0 + 3u * V_XI_STRIDE, a1 + 3u * V_XI_STRIDE, Ub + 3 * 3072, lane);

    // xi = 1: temp, px0 += M1, px1 += M1
    {
        float m[2][4][4];
        #pragma unroll
        for (int mi = 0; mi < 2; mi++)
            #pragma unroll
            for (int ni = 0; ni < 4; ni++)
                #pragma unroll
                for (int j = 0; j < 4; j++) m[mi][ni][j] = 0.f;
        gemm_xi(m, a0 + 1u * V_XI_STRIDE, a1 + 1u * V_XI_STRIDE, Ub + 1 * 3072, lane);
        #pragma unroll
        for (int mi = 0; mi < 2; mi++)
            #pragma unroll
            for (int ni = 0; ni < 4; ni++)
                #pragma unroll
                for (int j = 0; j < 4; j++) {
                    Y0[mi][ni][j] += m[mi][ni][j];
                    Y1[mi][ni][j] += m[mi][ni][j];
                }
    }
    // xi = 2: temp, px0 += M2, px1 -= M2
    {
        float m[2][4][4];
        #pragma unroll
        for (int mi = 0; mi < 2; mi++)
            #pragma unroll
            for (int ni = 0; ni < 4; ni++)
                #pragma unroll
                for (int j = 0; j < 4; j++) m[mi][ni][j] = 0.f;
        gemm_xi(m, a0 + 2u * V_XI_STRIDE, a1 + 2u * V_XI_STRIDE, Ub + 2 * 3072, lane);
        #pragma unroll
        for (int mi = 0; mi < 2; mi++)
            #pragma unroll
            for (int ni = 0; ni < 4; ni++)
                #pragma unroll
                for (int j = 0; j < 4; j++) {
                    Y0[mi][ni][j] += m[mi][ni][j];
                    Y1[mi][ni][j] -= m[mi][ni][j];
                }
    }

    // ---- epilogue: STG.64 of adjacent output-px pairs (fully coalesced) ----
    const int xg = x0 + 2 * (lane >> 2);
    #pragma unroll
    for (int mi = 0; mi < 2; mi++)
        #pragma unroll
        for (int yr = 0; yr < 2; yr++) {
            const int y = y0 + 4 * wm + 2 * mi + yr;
            #pragma unroll
            for (int ni = 0; ni < 4; ni++)
                #pragma unroll
                for (int j = 0; j < 2; j++) {
                    const int o = wn * 32 + ni * 8 + 2 * (lane & 3) + j;
                    float2 v = make_float2(Y0[mi][ni][yr * 2 + j],
                                           Y1[mi][ni][yr * 2 + j]);
                    *reinterpret_cast<float2*>(
                        out + ((size_t)(b * 64 + o) << 18) + ((size_t)y << 9) + xg) = v;
                }
        }
}

// ---------------------------------------------------------------------------
// Harness entry point.
//   d_in[0] = input  (4, 64, 512, 512) float
//   d_in[1] = style  (4, 64)           float
//   d_in[2] = weight (64, 64, 3, 3)    float
//   d_out   = (4, 64, 512, 512) float
// ---------------------------------------------------------------------------
extern "C" void kernel_launch(void* const* d_in, const int* in_sizes, int n_in,
                              void* d_out, int out_size) {
    const float* input  = (const float*)d_in[0];
    const float* style  = (const float*)d_in[1];
    const float* weight = (const float*)d_in[2];
    float* out = (float*)d_out;

    cudaFuncSetAttribute(conv_kernel, cudaFuncAttributeMaxDynamicSharedMemorySize,
                         CONV_SMEM);

    modulate_kernel<<<256, 256>>>(weight, style);
    conv_kernel<<<dim3(32, 64, 4), 128, CONV_SMEM>>>(input, out);
}

// round 14
// speedup vs baseline: 1.6820x; 1.0192x over previous
#include <cuda_runtime.h>
#include <cuda_fp16.h>
#include <cstdint>
#include <cstddef>

// Problem constants: B=4, I=64, O=64, K=3, H=W=512.
#define EPS_F 1e-8f

// ---------------------------------------------------------------------------
// Device scratch: x-Winograd-transformed modulated weights, packed so the TWO
// B fragments a warp needs per K-step are one LDG.128 per lane:
// uint4 index (per b, per xi): ((s*4 + npg)*32 + lane), s = kc*3 + ky,
// npg = o>>4. Within the uint4: words = { ni_even.hf0, ni_even.hf1,
// ni_odd.hf0, ni_odd.hf1 } where ni_even/odd = npg*2 + {0,1}, and lane l
// supplies kpair rows (l&3) / (l&3)+4 of the K16 step, o = ni*8 + (l>>2).
// xi=3 is stored NEGATED (A^T fold).
// ---------------------------------------------------------------------------
__device__ __align__(16) uint32_t g_wU[4 * 4 * 6144];                // 384 KB

__device__ __forceinline__ uint32_t smem_u32(const void* p) {
    uint32_t a;
    asm("{ .reg .u64 t; cvta.to.shared.u64 t, %1; cvt.u32.u64 %0, t; }"
        : "=r"(a) : "l"(p));
    return a;
}

// ---------------------------------------------------------------------------
// Kernel 1: modulate + demodulate + x-Winograd weight transform (U = G g).
// U0 = g0; U1 = (g0+g1+g2)/2; U2 = (g0-g1+g2)/2; U3 = -g2 (negated).
// ---------------------------------------------------------------------------
__global__ void modulate_kernel(const float* __restrict__ weight,   // (O=64, I=64, 3, 3)
                                const float* __restrict__ style) {  // (B=4, I=64)
    const int bo  = blockIdx.x;
    const int b   = bo >> 6;
    const int o   = bo & 63;
    const int tid = threadIdx.x;

    __shared__ float red[8];
    __shared__ float s_inv;

    float sum = 0.f;
    for (int idx = tid; idx < 576; idx += 256) {
        const int i = idx / 9;
        const float v = weight[o * 576 + idx] * style[b * 64 + i];
        sum += v * v;
    }
    #pragma unroll
    for (int off = 16; off; off >>= 1)
        sum += __shfl_down_sync(0xffffffffu, sum, off);
    if ((tid & 31) == 0) red[tid >> 5] = sum;
    __syncthreads();
    if (tid == 0) {
        float t = 0.f;
        #pragma unroll
        for (int k = 0; k < 8; k++) t += red[k];
        s_inv = rsqrtf(EPS_F + t);
    }
    __syncthreads();
    const float inv = s_inv;

    // 96 items: (cpair cp 0..31, ky 0..2)
    if (tid < 96) {
        const int cp = tid / 3;
        const int ky = tid - 3 * cp;
        const int c0 = 2 * cp;
        const float s0 = style[b * 64 + c0] * inv;
        const float s1 = style[b * 64 + c0 + 1] * inv;
        const float* w0 = weight + (o * 64 + c0) * 9 + ky * 3;
        const float g00 = w0[0] * s0, g01 = w0[1] * s0, g02 = w0[2] * s0;
        const float g10 = w0[9] * s1, g11 = w0[10] * s1, g12 = w0[11] * s1;

        float u0[4], u1[4];
        u0[0] = g00; u0[1] = 0.5f * (g00 + g01 + g02);
        u0[2] = 0.5f * (g00 - g01 + g02); u0[3] = -g02;    // xi=3 negated
        u1[0] = g10; u1[1] = 0.5f * (g10 + g11 + g12);
        u1[2] = 0.5f * (g10 - g11 + g12); u1[3] = -g12;    // xi=3 negated

        const int kc   = cp >> 3;               // channel 16-block (K16 step col)
        const int r    = cp & 7;                // kpair row within step
        const int t    = r & 3;
        const int hf   = r >> 2;
        const int s    = kc * 3 + ky;           // K-step index (kc-major)
        const int ln   = ((o & 7) << 2) | t;    // consuming lane
        const int npg  = o >> 4;                // ni-pair group
        const int wsel = ((o >> 3) & 1) * 2 + hf;
        #pragma unroll
        for (int xi = 0; xi < 4; xi++) {
            __half2 h = __floats2half2_rn(u0[xi], u1[xi]);
            g_wU[(size_t)(b * 4 + xi) * 6144
                 + (size_t)(((s * 4 + npg) * 32 + ln) * 4 + wsel)] =
                *reinterpret_cast<uint32_t*>(&h);
        }
    }
}

// ---------------------------------------------------------------------------
// Kernel 2: x-Winograd F(2,3) fp16 mma.sync conv, direct from NCHW fp32.
// 128 threads = 4 warps, each m32 x n32. B fragments fetched as LDG.128
// ni-pairs (2 loads/step instead of 4); K-loop kc-major.
//
// CTA tile: 8 rows x 16 px, M = 64 x-tiles. Per xi: GEMM M64 x N64 x K192.
// A^T fold: xi=0 -> Y0 (px0), xi=3 (pre-negated) -> Y1 (px1),
//           xi=1 -> temp, +Y0 +Y1;  xi=2 -> temp, +Y0 -Y1.
// V smem: V[xi][r(10)][xt(8)][c(64)] fp16, xt stride 144 B, row stride 1168 B.
// Warp (wm = wid&1, wn = wid>>1): rows [4wm, 4wm+4) x o range [wn*32, +32).
// ---------------------------------------------------------------------------
static constexpr int V_ROW_STRIDE = 8 * 144 + 16;        // 1168 B
static constexpr int V_XI_STRIDE  = 10 * V_ROW_STRIDE;   // 11680 B
static constexpr int CONV_SMEM    = 4 * V_XI_STRIDE;     // 46720

#define LDSM4(dst, addr) \
    asm volatile("ldmatrix.sync.aligned.m8n8.x4.shared.b16 {%0,%1,%2,%3}, [%4];" \
        : "=r"((dst)[0]), "=r"((dst)[1]), "=r"((dst)[2]), "=r"((dst)[3]) \
        : "r"(addr))

// One xi-GEMM, m32n32: 12 K-steps (kc-major), A (2 m-tiles) from smem via
// ldmatrix, B via one LDG.128 per ni-pair; both double-buffered 1 step ahead.
__device__ __forceinline__ void gemm_xi(float (&acc)[2][4][4],
                                        uint32_t a0, uint32_t a1,
                                        const uint4* __restrict__ Ub) {
    uint32_t af[2][2][4];
    uint4    bv[2][2];
    LDSM4(af[0][0], a0);
    LDSM4(af[0][1], a1);
    bv[0][0] = __ldg(Ub);
    bv[0][1] = __ldg(Ub + 32);

    #pragma unroll
    for (int s = 0; s < 12; s++) {
        const int cur = s & 1, nxt = cur ^ 1;
        if (s < 11) {
            const int s1 = s + 1;
            const uint32_t off = (uint32_t)((s1 % 3) * V_ROW_STRIDE + (s1 / 3) * 32);
            LDSM4(af[nxt][0], a0 + off);
            LDSM4(af[nxt][1], a1 + off);
            bv[nxt][0] = __ldg(Ub + s1 * 128);
            bv[nxt][1] = __ldg(Ub + s1 * 128 + 32);
        }
        #pragma unroll
        for (int np = 0; np < 2; np++) {
            const uint4 q = bv[cur][np];
            #pragma unroll
            for (int mi = 0; mi < 2; mi++) {
                asm volatile(
                    "mma.sync.aligned.m16n8k16.row.col.f32.f16.f16.f32 "
                    "{%0,%1,%2,%3}, {%4,%5,%6,%7}, {%8,%9}, {%0,%1,%2,%3};"
                    : "+f"(acc[mi][np*2+0][0]), "+f"(acc[mi][np*2+0][1]),
                      "+f"(acc[mi][np*2+0][2]), "+f"(acc[mi][np*2+0][3])
                    : "r"(af[cur][mi][0]), "r"(af[cur][mi][1]),
                      "r"(af[cur][mi][2]), "r"(af[cur][mi][3]),
                      "r"(q.x), "r"(q.y));
                asm volatile(
                    "mma.sync.aligned.m16n8k16.row.col.f32.f16.f16.f32 "
                    "{%0,%1,%2,%3}, {%4,%5,%6,%7}, {%8,%9}, {%0,%1,%2,%3};"
                    : "+f"(acc[mi][np*2+1][0]), "+f"(acc[mi][np*2+1][1]),
                      "+f"(acc[mi][np*2+1][2]), "+f"(acc[mi][np*2+1][3])
                    : "r"(af[cur][mi][0]), "r"(af[cur][mi][1]),
                      "r"(af[cur][mi][2]), "r"(af[cur][mi][3]),
                      "r"(q.z), "r"(q.w));
            }
        }
    }
}

__global__ __launch_bounds__(128, 3)
void conv_kernel(const float* __restrict__ input,   // (4, 64, 512, 512) fp32 NCHW
                 float* __restrict__ out) {         // (4, 64, 512, 512)
    extern __shared__ __align__(16) char dsm[];

    const int tid  = threadIdx.x;
    const int lane = tid & 31;
    const int wid  = tid >> 5;
    const int b    = blockIdx.z;
    const int y0   = blockIdx.y << 3;
    const int x0   = blockIdx.x << 4;

    const uint32_t vsm0 = smem_u32(dsm);

    // ---- build V from NCHW fp32 ----
    // item = (r 0..9, cpair 0..31, xhalf 0..1): 640 items = 128 thr x 5.
    {
        const float* in_b = input + (size_t)b * (64 * 512 * 512);
        #pragma unroll
        for (int it = 0; it < 5; it++) {
            const int idx = it * 128 + tid;
            const int r   = idx >> 6;
            const int rm  = idx & 63;
            const int cp  = rm >> 1;
            const int xh  = rm & 1;
            const int gy  = y0 - 1 + r;
            const int gxb = x0 + 8 * xh - 4;
            const bool rowok = ((unsigned)gy < 512u);
            const float* p0 = in_b + ((size_t)(2 * cp) << 18) + ((size_t)gy << 9);
            const float* p1 = p0 + ((size_t)1 << 18);
            float f0[16], f1[16];
            #pragma unroll
            for (int q = 0; q < 4; q++) {
                const int gx = gxb + 4 * q;
                float4 v0 = make_float4(0.f, 0.f, 0.f, 0.f);
                float4 v1 = make_float4(0.f, 0.f, 0.f, 0.f);
                if (rowok && (unsigned)gx < 512u) {
                    v0 = *reinterpret_cast<const float4*>(p0 + gx);
                    v1 = *reinterpret_cast<const float4*>(p1 + gx);
                }
                f0[4*q] = v0.x; f0[4*q+1] = v0.y; f0[4*q+2] = v0.z; f0[4*q+3] = v0.w;
                f1[4*q] = v1.x; f1[4*q+1] = v1.y; f1[4*q+2] = v1.z; f1[4*q+3] = v1.w;
            }
            const uint32_t vbase = vsm0 + (uint32_t)(r * V_ROW_STRIDE + cp * 4);
            #pragma unroll
            for (int xq = 0; xq < 4; xq++) {
                const int i0 = 2 * xq + 3;             // d(-1) of window
                const int xt = 4 * xh + xq;
                const float a0 = f0[i0], a1 = f0[i0+1], a2 = f0[i0+2], a3 = f0[i0+3];
                const float c0 = f1[i0], c1 = f1[i0+1], c2 = f1[i0+2], c3 = f1[i0+3];
                __half2 h0 = __floats2half2_rn(a0 - a2, c0 - c2);
                __half2 h1 = __floats2half2_rn(a1 + a2, c1 + c2);
                __half2 h2 = __floats2half2_rn(a2 - a1, c2 - c1);
                __half2 h3 = __floats2half2_rn(a1 - a3, c1 - c3);
                const uint32_t va = vbase + (uint32_t)(xt * 144);
                asm volatile("st.shared.u32 [%0], %1;"
                             :: "r"(va),                 "r"(*(uint32_t*)&h0));
                asm volatile("st.shared.u32 [%0], %1;"
                             :: "r"(va + V_XI_STRIDE),   "r"(*(uint32_t*)&h1));
                asm volatile("st.shared.u32 [%0], %1;"
                             :: "r"(va + 2*V_XI_STRIDE), "r"(*(uint32_t*)&h2));
                asm volatile("st.shared.u32 [%0], %1;"
                             :: "r"(va + 3*V_XI_STRIDE), "r"(*(uint32_t*)&h3));
            }
        }
    }
    __syncthreads();      // the ONLY barrier

    const int wm = wid & 1;    // m: rows [4wm, 4wm+4)
    const int wn = wid >> 1;   // n: o range [wn*32, wn*32+32)

    // ldmatrix A lane bases for the 2 m16-tiles of this warp.
    const uint32_t aCom = vsm0
        + (uint32_t)((((lane & 15) & 7) * 144) + (lane >> 4) * 16);
    const uint32_t a0 = aCom
        + (uint32_t)((4 * wm + ((lane & 15) >> 3)) * V_ROW_STRIDE);
    const uint32_t a1 = a0 + (uint32_t)(2 * V_ROW_STRIDE);

    // U fragment base for this warp (uint4 units; 1536 per xi)
    const uint4* Ub = reinterpret_cast<const uint4*>(g_wU)
                      + (size_t)(b * 4) * 1536 + (size_t)(wn * 2) * 32 + lane;

    float Y0[2][4][4], Y1[2][4][4];
    #pragma unroll
    for (int mi = 0; mi < 2; mi++)
        #pragma unroll
        for (int ni = 0; ni < 4; ni++)
            #pragma unroll
            for (int j = 0; j < 4; j++) { Y0[mi][ni][j] = 0.f; Y1[mi][ni][j] = 0.f; }

    // xi = 0: directly into Y0 (px0 += M0)
    gemm_xi(Y0, a0, a1, Ub);
    // xi = 3 (pre-negated): directly into Y1 (px1 -= M3)
    gemm_xi(Y1, a0 + 3u * V_XI_STRIDE, a1 + 3u * V_XI_STRIDE, Ub + 3 * 1536);

    // xi = 1: temp, px0 += M1, px1 += M1
    {
        float m[2][4][4];
        #pragma unroll
        for (int mi = 0; mi < 2; mi++)
            #pragma unroll
            for (int ni = 0; ni < 4; ni++)
                #pragma unroll
                for (int j = 0; j < 4; j++) m[mi][ni][j] = 0.f;
        gemm_xi(m, a0 + 1u * V_XI_STRIDE, a1 + 1u * V_XI_STRIDE, Ub + 1 * 1536);
        #pragma unroll
        for (int mi = 0; mi < 2; mi++)
            #pragma unroll
            for (int ni = 0; ni < 4; ni++)
                #pragma unroll
                for (int j = 0; j < 4; j++) {
                    Y0[mi][ni][j] += m[mi][ni][j];
                    Y1[mi][ni][j] += m[mi][ni][j];
                }
    }
    // xi = 2: temp, px0 += M2, px1 -= M2
    {
        float m[2][4][4];
        #pragma unroll
        for (int mi = 0; mi < 2; mi++)
            #pragma unroll
            for (int ni = 0; ni < 4; ni++)
                #pragma unroll
                for (int j = 0; j < 4; j++) m[mi][ni][j] = 0.f;
        gemm_xi(m, a0 + 2u * V_XI_STRIDE, a1 + 2u * V_XI_STRIDE, Ub + 2 * 1536);
        #pragma unroll
        for (int mi = 0; mi < 2; mi++)
            #pragma unroll
            for (int ni = 0; ni < 4; ni++)
                #pragma unroll
                for (int j = 0; j < 4; j++) {
                    Y0[mi][ni][j] += m[mi][ni][j];
                    Y1[mi][ni][j] -= m[mi][ni][j];
                }
    }

    // ---- epilogue: STG.64 of adjacent output-px pairs (fully coalesced) ----
    const int xg = x0 + 2 * (lane >> 2);
    #pragma unroll
    for (int mi = 0; mi < 2; mi++)
        #pragma unroll
        for (int yr = 0; yr < 2; yr++) {
            const int y = y0 + 4 * wm + 2 * mi + yr;
            #pragma unroll
            for (int ni = 0; ni < 4; ni++)
                #pragma unroll
                for (int j = 0; j < 2; j++) {
                    const int o = wn * 32 + ni * 8 + 2 * (lane & 3) + j;
                    float2 v = make_float2(Y0[mi][ni][yr * 2 + j],
                                           Y1[mi][ni][yr * 2 + j]);
                    *reinterpret_cast<float2*>(
                        out + ((size_t)(b * 64 + o) << 18) + ((size_t)y << 9) + xg) = v;
                }
        }
}

// ---------------------------------------------------------------------------
// Harness entry point.
//   d_in[0] = input  (4, 64, 512, 512) float
//   d_in[1] = style  (4, 64)           float
//   d_in[2] = weight (64, 64, 3, 3)    float
//   d_out   = (4, 64, 512, 512) float
// ---------------------------------------------------------------------------
extern "C" void kernel_launch(void* const* d_in, const int* in_sizes, int n_in,
                              void* d_out, int out_size) {
    const float* input  = (const float*)d_in[0];
    const float* style  = (const float*)d_in[1];
    const float* weight = (const float*)d_in[2];
    float* out = (float*)d_out;

    cudaFuncSetAttribute(conv_kernel, cudaFuncAttributeMaxDynamicSharedMemorySize,
                         CONV_SMEM);

    modulate_kernel<<<256, 256>>>(weight, style);
    conv_kernel<<<dim3(32, 64, 4), 128, CONV_SMEM>>>(input, out);
}